// round 12
// baseline (speedup 1.0000x reference)
#include <cuda_runtime.h>
#include <cuda_fp16.h>
#include <cstdint>
#include <math.h>

#define BATCH   4096
#define IN_DIM  512
#define NH      32
#define OUT_DIM 512
#define KTOT    (IN_DIM * NH * 2)   // 32768

#define BM 128
#define BN 128
#define BK 64
#define THREADS 384                 // 256 consumers + 128 producers
#define STAGES 4
#define STAGE_SZ 32768              // A 16KB + B 16KB
#define SM_TOTAL (STAGES * STAGE_SZ + 512)

__device__ __half g_Wt[(size_t)OUT_DIM * KTOT];   // [n][k] 32 MB

__device__ __forceinline__ uint32_t smem_u32(const void* p) {
    uint32_t a;
    asm("{ .reg .u64 t; cvta.to.shared.u64 t, %1; cvt.u32.u64 %0, t; }" : "=r"(a) : "l"(p));
    return a;
}
#define BAR_SYNC(id, cnt)   asm volatile("bar.sync %0, %1;"   :: "r"(id), "r"(cnt) : "memory")
#define BAR_ARRIVE(id, cnt) asm volatile("bar.arrive %0, %1;" :: "r"(id), "r"(cnt) : "memory")

// ---------------- kernel 1: transpose + fp16 convert of W ----------------
__global__ void __launch_bounds__(256)
w_prep_kernel(const float* __restrict__ W) {      // W: [KTOT, OUT_DIM]
    __shared__ float t[32][33];
    int k0 = blockIdx.x * 32;
    int n0 = blockIdx.y * 32;
    int tx = threadIdx.x, ty = threadIdx.y;       // block (32, 8)
    #pragma unroll
    for (int r = 0; r < 4; ++r)
        t[ty + 8 * r][tx] = W[(size_t)(k0 + ty + 8 * r) * OUT_DIM + n0 + tx];
    __syncthreads();
    #pragma unroll
    for (int r = 0; r < 4; ++r) {
        float v = t[tx][ty + 8 * r];
        g_Wt[(size_t)(n0 + ty + 8 * r) * KTOT + k0 + tx] = __float2half_rn(v);
    }
}

// ---------------- kernel 2: warp-specialized fused trig + HMMA GEMM ----------------
// 4 stages at s*32KB: A [128m][64k] swizzled (16KB) + B [128n][64k] swizzled (16KB)
// bias (128 f32) at 128KB. Epilogue reduction reuses stage area.
// Named barriers: full[s] = 1+s (1..4), empty[s] = 5+s (5..8), both count 384;
// consumer-only barrier id 9, count 256.
__global__ void __launch_bounds__(THREADS, 1)
fkan_ws_kernel(const float* __restrict__ X,
               const float* __restrict__ bias,
               float* __restrict__ out)
{
    extern __shared__ char smem[];
    const uint32_t sb = smem_u32(smem);
    const int tid = threadIdx.x;
    const int bn0 = blockIdx.x * BN;
    const int bm0 = blockIdx.y * BM;

    if (tid >= 256) {
        // ================= PRODUCER (warps 8..11) =================
        const int p = tid - 256;                  // 0..127
        ((float*)(smem + STAGES * STAGE_SZ))[p] = bias[bn0 + p];

        const uint32_t swz = (uint32_t)(p & 7) << 4;
        const char* bsrc0 = (const char*)(g_Wt + (size_t)(bn0 + p) * KTOT);
        const float* xrow = X + (size_t)(bm0 + p) * IN_DIM;

        for (int i = 0; i < IN_DIM; ++i) {
            const int s = i & (STAGES - 1);
            if (i >= STAGES) BAR_SYNC(5 + s, 384);    // wait empty[s]
            const uint32_t stg = sb + s * STAGE_SZ;

            // B row p -> stage B (swizzled 16B granules), async
            const char* src = bsrc0 + (size_t)i * 128;
            uint32_t bdst = stg + 16384 + (uint32_t)p * 128;
            #pragma unroll
            for (int j = 0; j < 8; ++j)
                asm volatile("cp.async.cg.shared.global [%0], [%1], 16;"
                             :: "r"(bdst + ((16u * j) ^ swz)), "l"(src + 16 * j) : "memory");
            asm volatile("cp.async.commit_group;" ::: "memory");

            // A row p: harmonics 1..32 via two independent 16-step chains (step 2x)
            float x = xrow[i];
            float s1, c1;
            __sincosf(x, &s1, &c1);
            float cd = fmaf(-2.f * s1, s1, 1.f);      // cos 2x
            float sd = 2.f * s1 * c1;                 // sin 2x
            float ca = c1, sa = s1;                   // odd harmonics 1,3,..
            float cb = cd, sb2 = sd;                  // even harmonics 2,4,..
            uint32_t buf[32];
            #pragma unroll
            for (int g = 0; g < 16; ++g) {
                __half2 ha = __floats2half2_rn(ca, sa);
                __half2 hb = __floats2half2_rn(cb, sb2);
                buf[2 * g]     = *(uint32_t*)&ha;     // harmonic 2g+1
                buf[2 * g + 1] = *(uint32_t*)&hb;     // harmonic 2g+2
                float can = fmaf(ca, cd, -sa * sd);
                float san = fmaf(sa, cd,  ca * sd);
                float cbn = fmaf(cb, cd, -sb2 * sd);
                float sbn = fmaf(sb2, cd, cb * sd);
                ca = can; sa = san; cb = cbn; sb2 = sbn;
            }
            uint32_t adst = stg + (uint32_t)p * 128;
            #pragma unroll
            for (int j = 0; j < 8; ++j) {
                uint32_t d = adst + ((16u * j) ^ swz);
                asm volatile("st.shared.v4.b32 [%0], {%1,%2,%3,%4};"
                             :: "r"(d), "r"(buf[4*j]), "r"(buf[4*j+1]),
                                "r"(buf[4*j+2]), "r"(buf[4*j+3]) : "memory");
            }
            asm volatile("cp.async.wait_group 0;" ::: "memory");
            BAR_ARRIVE(1 + s, 384);                   // full[s]
        }
        return;
    }

    // ================= CONSUMER (warps 0..7) =================
    const int wid = tid >> 5, l = tid & 31;
    const int wk = wid & 1;
    const int wm = (wid >> 1) & 1;
    const int wn = wid >> 2;

    const int ar  = ((l >> 3) & 1) * 8 + (l & 7);
    const int akx = (l >> 4) << 4;
    const int br  = ((l >> 4) & 1) * 8 + (l & 7);
    const int bkx = ((l >> 3) & 1) << 4;
    const int sw  = (l & 7) << 4;

    float acc[4][8][4];
    #pragma unroll
    for (int mf = 0; mf < 4; ++mf)
        #pragma unroll
        for (int nf = 0; nf < 8; ++nf)
            #pragma unroll
            for (int q = 0; q < 4; ++q) acc[mf][nf][q] = 0.f;

    for (int i = 0; i < IN_DIM; ++i) {
        const int s = i & (STAGES - 1);
        BAR_SYNC(1 + s, 384);                         // wait full[s]
        uint32_t sA = sb + s * STAGE_SZ;
        uint32_t sB = sA + 16384;
        #pragma unroll
        for (int kk = 0; kk < 2; ++kk) {
            const int kbyte = wk * 64 + kk * 32;
            uint32_t a[4][4];
            #pragma unroll
            for (int mf = 0; mf < 4; ++mf) {
                uint32_t addr = sA + (uint32_t)(wm * 64 + mf * 16 + ar) * 128
                              + (uint32_t)((kbyte + akx) ^ sw);
                asm volatile("ldmatrix.sync.aligned.m8n8.x4.shared.b16 {%0,%1,%2,%3}, [%4];"
                    : "=r"(a[mf][0]), "=r"(a[mf][1]), "=r"(a[mf][2]), "=r"(a[mf][3])
                    : "r"(addr));
            }
            uint32_t b[8][2];
            #pragma unroll
            for (int pj = 0; pj < 4; ++pj) {
                uint32_t addr = sB + (uint32_t)(wn * 64 + pj * 16 + br) * 128
                              + (uint32_t)((kbyte + bkx) ^ sw);
                uint32_t r0, r1, r2, r3;
                asm volatile("ldmatrix.sync.aligned.m8n8.x4.shared.b16 {%0,%1,%2,%3}, [%4];"
                    : "=r"(r0), "=r"(r1), "=r"(r2), "=r"(r3) : "r"(addr));
                b[2 * pj][0] = r0;     b[2 * pj][1] = r1;
                b[2 * pj + 1][0] = r2; b[2 * pj + 1][1] = r3;
            }
            #pragma unroll
            for (int mf = 0; mf < 4; ++mf)
                #pragma unroll
                for (int nf = 0; nf < 8; ++nf)
                    asm volatile(
                        "mma.sync.aligned.m16n8k16.row.col.f32.f16.f16.f32 "
                        "{%0,%1,%2,%3}, {%4,%5,%6,%7}, {%8,%9}, {%0,%1,%2,%3};"
                        : "+f"(acc[mf][nf][0]), "+f"(acc[mf][nf][1]),
                          "+f"(acc[mf][nf][2]), "+f"(acc[mf][nf][3])
                        : "r"(a[mf][0]), "r"(a[mf][1]), "r"(a[mf][2]), "r"(a[mf][3]),
                          "r"(b[nf][0]), "r"(b[nf][1]));
        }
        BAR_ARRIVE(5 + s, 384);                       // empty[s]
    }

    // ---- epilogue (consumers only): k-split reduction + bias + store ----
    BAR_SYNC(9, 256);
    float* red = (float*)(smem + (size_t)(wm * 2 + wn) * 16384);
    const int lr = l >> 2, lc = 2 * (l & 3);

    if (wk == 1) {
        #pragma unroll
        for (int mf = 0; mf < 4; ++mf)
            #pragma unroll
            for (int nf = 0; nf < 8; ++nf) {
                int r0 = mf * 16 + lr, c = nf * 8 + lc;
                *(float2*)&red[r0 * 64 + c]       = make_float2(acc[mf][nf][0], acc[mf][nf][1]);
                *(float2*)&red[(r0 + 8) * 64 + c] = make_float2(acc[mf][nf][2], acc[mf][nf][3]);
            }
    }
    BAR_SYNC(9, 256);
    if (wk == 0) {
        const float* biasS = (const float*)(smem + STAGES * STAGE_SZ);
        #pragma unroll
        for (int mf = 0; mf < 4; ++mf) {
            #pragma unroll
            for (int nf = 0; nf < 8; ++nf) {
                int r0 = mf * 16 + lr, c = nf * 8 + lc;
                int nloc = wn * 64 + c;
                float2 p0 = *(const float2*)&red[r0 * 64 + c];
                float2 p1 = *(const float2*)&red[(r0 + 8) * 64 + c];
                int m0 = bm0 + wm * 64 + r0;
                float2 v0 = { acc[mf][nf][0] + p0.x + biasS[nloc],
                              acc[mf][nf][1] + p0.y + biasS[nloc + 1] };
                float2 v1 = { acc[mf][nf][2] + p1.x + biasS[nloc],
                              acc[mf][nf][3] + p1.y + biasS[nloc + 1] };
                *(float2*)(out + (size_t)m0 * OUT_DIM + bn0 + nloc)       = v0;
                *(float2*)(out + (size_t)(m0 + 8) * OUT_DIM + bn0 + nloc) = v1;
            }
        }
    }
}

// ---------------- launcher ----------------
extern "C" void kernel_launch(void* const* d_in, const int* in_sizes, int n_in,
                              void* d_out, int out_size) {
    const float* X    = (const float*)d_in[0];
    const float* W    = (const float*)d_in[1];
    const float* bias = (const float*)d_in[2];
    float* out = (float*)d_out;
    (void)in_sizes; (void)n_in; (void)out_size;

    dim3 pgrid(KTOT / 32, OUT_DIM / 32);
    w_prep_kernel<<<pgrid, dim3(32, 8)>>>(W);

    cudaFuncSetAttribute(fkan_ws_kernel,
                         cudaFuncAttributeMaxDynamicSharedMemorySize, SM_TOTAL);
    dim3 grid(OUT_DIM / BN, BATCH / BM);
    fkan_ws_kernel<<<grid, THREADS, SM_TOTAL>>>(X, bias, out);
}

// round 13
// speedup vs baseline: 1.0013x; 1.0013x over previous
#include <cuda_runtime.h>
#include <cuda_fp16.h>
#include <cstdint>
#include <math.h>

#define BATCH   4096
#define IN_DIM  512
#define NH      32
#define OUT_DIM 512
#define KTOT    (IN_DIM * NH * 2)   // 32768

#define BM 128
#define BN 128
#define BK 64
#define THREADS 384                 // 256 consumers + 128 producers
#define STAGES 4
#define STAGE_SZ 32768              // A 16KB + B 16KB
#define SM_TOTAL (STAGES * STAGE_SZ + 512)

__device__ __half g_Wt[(size_t)OUT_DIM * KTOT];   // [n][k] 32 MB

__device__ __forceinline__ uint32_t smem_u32(const void* p) {
    uint32_t a;
    asm("{ .reg .u64 t; cvta.to.shared.u64 t, %1; cvt.u32.u64 %0, t; }" : "=r"(a) : "l"(p));
    return a;
}
#define BAR_SYNC(id, cnt)   asm volatile("bar.sync %0, %1;"   :: "r"(id), "r"(cnt) : "memory")
#define BAR_ARRIVE(id, cnt) asm volatile("bar.arrive %0, %1;" :: "r"(id), "r"(cnt) : "memory")

// ---------------- kernel 1: transpose + fp16 convert of W ----------------
__global__ void __launch_bounds__(256)
w_prep_kernel(const float* __restrict__ W) {      // W: [KTOT, OUT_DIM]
    __shared__ float t[32][33];
    int k0 = blockIdx.x * 32;
    int n0 = blockIdx.y * 32;
    int tx = threadIdx.x, ty = threadIdx.y;       // block (32, 8)
    #pragma unroll
    for (int r = 0; r < 4; ++r)
        t[ty + 8 * r][tx] = W[(size_t)(k0 + ty + 8 * r) * OUT_DIM + n0 + tx];
    __syncthreads();
    #pragma unroll
    for (int r = 0; r < 4; ++r) {
        float v = t[tx][ty + 8 * r];
        g_Wt[(size_t)(n0 + ty + 8 * r) * KTOT + k0 + tx] = __float2half_rn(v);
    }
}

// ---------------- kernel 2: warp-specialized fused trig + HMMA GEMM ----------------
// 4 stages at s*32KB: A [128m][64k] swizzled (16KB) + B [128n][64k] swizzled (16KB)
// bias (128 f32) at 128KB. Epilogue reduction reuses stage area.
// Named barriers: full[s] = 1+s (1..4), empty[s] = 5+s (5..8), both count 384;
// consumer-only barrier id 9, count 256.
__global__ void __launch_bounds__(THREADS, 1)
fkan_ws_kernel(const float* __restrict__ X,
               const float* __restrict__ bias,
               float* __restrict__ out)
{
    extern __shared__ char smem[];
    const uint32_t sb = smem_u32(smem);
    const int tid = threadIdx.x;
    const int bn0 = blockIdx.x * BN;
    const int bm0 = blockIdx.y * BM;

    if (tid >= 256) {
        // ================= PRODUCER (warps 8..11) =================
        const int p = tid - 256;                  // 0..127
        ((float*)(smem + STAGES * STAGE_SZ))[p] = bias[bn0 + p];

        const uint32_t swz = (uint32_t)(p & 7) << 4;
        const char* bsrc0 = (const char*)(g_Wt + (size_t)(bn0 + p) * KTOT);
        const float* xrow = X + (size_t)(bm0 + p) * IN_DIM;

        for (int i = 0; i < IN_DIM; ++i) {
            const int s = i & (STAGES - 1);
            if (i >= STAGES) BAR_SYNC(5 + s, 384);    // wait empty[s]
            const uint32_t stg = sb + s * STAGE_SZ;

            // B row p -> stage B (swizzled 16B granules), async
            const char* src = bsrc0 + (size_t)i * 128;
            uint32_t bdst = stg + 16384 + (uint32_t)p * 128;
            #pragma unroll
            for (int j = 0; j < 8; ++j)
                asm volatile("cp.async.cg.shared.global [%0], [%1], 16;"
                             :: "r"(bdst + ((16u * j) ^ swz)), "l"(src + 16 * j) : "memory");
            asm volatile("cp.async.commit_group;" ::: "memory");

            // A row p: harmonics 1..32 via two independent 16-step chains (step 2x)
            float x = xrow[i];
            float s1, c1;
            __sincosf(x, &s1, &c1);
            float cd = fmaf(-2.f * s1, s1, 1.f);      // cos 2x
            float sd = 2.f * s1 * c1;                 // sin 2x
            float ca = c1, sa = s1;                   // odd harmonics 1,3,..
            float cb = cd, sb2 = sd;                  // even harmonics 2,4,..
            uint32_t buf[32];
            #pragma unroll
            for (int g = 0; g < 16; ++g) {
                __half2 ha = __floats2half2_rn(ca, sa);
                __half2 hb = __floats2half2_rn(cb, sb2);
                buf[2 * g]     = *(uint32_t*)&ha;     // harmonic 2g+1
                buf[2 * g + 1] = *(uint32_t*)&hb;     // harmonic 2g+2
                float can = fmaf(ca, cd, -sa * sd);
                float san = fmaf(sa, cd,  ca * sd);
                float cbn = fmaf(cb, cd, -sb2 * sd);
                float sbn = fmaf(sb2, cd, cb * sd);
                ca = can; sa = san; cb = cbn; sb2 = sbn;
            }
            uint32_t adst = stg + (uint32_t)p * 128;
            #pragma unroll
            for (int j = 0; j < 8; ++j) {
                uint32_t d = adst + ((16u * j) ^ swz);
                asm volatile("st.shared.v4.b32 [%0], {%1,%2,%3,%4};"
                             :: "r"(d), "r"(buf[4*j]), "r"(buf[4*j+1]),
                                "r"(buf[4*j+2]), "r"(buf[4*j+3]) : "memory");
            }
            asm volatile("cp.async.wait_group 0;" ::: "memory");
            BAR_ARRIVE(1 + s, 384);                   // full[s]
        }
        return;
    }

    // ================= CONSUMER (warps 0..7) =================
    const int wid = tid >> 5, l = tid & 31;
    const int wk = wid & 1;
    const int wm = (wid >> 1) & 1;
    const int wn = wid >> 2;

    const int ar  = ((l >> 3) & 1) * 8 + (l & 7);
    const int akx = (l >> 4) << 4;
    const int br  = ((l >> 4) & 1) * 8 + (l & 7);
    const int bkx = ((l >> 3) & 1) << 4;
    const int sw  = (l & 7) << 4;

    float acc[4][8][4];
    #pragma unroll
    for (int mf = 0; mf < 4; ++mf)
        #pragma unroll
        for (int nf = 0; nf < 8; ++nf)
            #pragma unroll
            for (int q = 0; q < 4; ++q) acc[mf][nf][q] = 0.f;

    for (int i = 0; i < IN_DIM; ++i) {
        const int s = i & (STAGES - 1);
        BAR_SYNC(1 + s, 384);                         // wait full[s]
        uint32_t sA = sb + s * STAGE_SZ;
        uint32_t sB = sA + 16384;
        #pragma unroll
        for (int kk = 0; kk < 2; ++kk) {
            const int kbyte = wk * 64 + kk * 32;
            uint32_t a[4][4];
            #pragma unroll
            for (int mf = 0; mf < 4; ++mf) {
                uint32_t addr = sA + (uint32_t)(wm * 64 + mf * 16 + ar) * 128
                              + (uint32_t)((kbyte + akx) ^ sw);
                asm volatile("ldmatrix.sync.aligned.m8n8.x4.shared.b16 {%0,%1,%2,%3}, [%4];"
                    : "=r"(a[mf][0]), "=r"(a[mf][1]), "=r"(a[mf][2]), "=r"(a[mf][3])
                    : "r"(addr));
            }
            uint32_t b[8][2];
            #pragma unroll
            for (int pj = 0; pj < 4; ++pj) {
                uint32_t addr = sB + (uint32_t)(wn * 64 + pj * 16 + br) * 128
                              + (uint32_t)((kbyte + bkx) ^ sw);
                uint32_t r0, r1, r2, r3;
                asm volatile("ldmatrix.sync.aligned.m8n8.x4.shared.b16 {%0,%1,%2,%3}, [%4];"
                    : "=r"(r0), "=r"(r1), "=r"(r2), "=r"(r3) : "r"(addr));
                b[2 * pj][0] = r0;     b[2 * pj][1] = r1;
                b[2 * pj + 1][0] = r2; b[2 * pj + 1][1] = r3;
            }
            #pragma unroll
            for (int mf = 0; mf < 4; ++mf)
                #pragma unroll
                for (int nf = 0; nf < 8; ++nf)
                    asm volatile(
                        "mma.sync.aligned.m16n8k16.row.col.f32.f16.f16.f32 "
                        "{%0,%1,%2,%3}, {%4,%5,%6,%7}, {%8,%9}, {%0,%1,%2,%3};"
                        : "+f"(acc[mf][nf][0]), "+f"(acc[mf][nf][1]),
                          "+f"(acc[mf][nf][2]), "+f"(acc[mf][nf][3])
                        : "r"(a[mf][0]), "r"(a[mf][1]), "r"(a[mf][2]), "r"(a[mf][3]),
                          "r"(b[nf][0]), "r"(b[nf][1]));
        }
        BAR_ARRIVE(5 + s, 384);                       // empty[s]
    }

    // ---- epilogue (consumers only): k-split reduction + bias + store ----
    BAR_SYNC(9, 256);
    float* red = (float*)(smem + (size_t)(wm * 2 + wn) * 16384);
    const int lr = l >> 2, lc = 2 * (l & 3);

    if (wk == 1) {
        #pragma unroll
        for (int mf = 0; mf < 4; ++mf)
            #pragma unroll
            for (int nf = 0; nf < 8; ++nf) {
                int r0 = mf * 16 + lr, c = nf * 8 + lc;
                *(float2*)&red[r0 * 64 + c]       = make_float2(acc[mf][nf][0], acc[mf][nf][1]);
                *(float2*)&red[(r0 + 8) * 64 + c] = make_float2(acc[mf][nf][2], acc[mf][nf][3]);
            }
    }
    BAR_SYNC(9, 256);
    if (wk == 0) {
        const float* biasS = (const float*)(smem + STAGES * STAGE_SZ);
        #pragma unroll
        for (int mf = 0; mf < 4; ++mf) {
            #pragma unroll
            for (int nf = 0; nf < 8; ++nf) {
                int r0 = mf * 16 + lr, c = nf * 8 + lc;
                int nloc = wn * 64 + c;
                float2 p0 = *(const float2*)&red[r0 * 64 + c];
                float2 p1 = *(const float2*)&red[(r0 + 8) * 64 + c];
                int m0 = bm0 + wm * 64 + r0;
                float2 v0 = { acc[mf][nf][0] + p0.x + biasS[nloc],
                              acc[mf][nf][1] + p0.y + biasS[nloc + 1] };
                float2 v1 = { acc[mf][nf][2] + p1.x + biasS[nloc],
                              acc[mf][nf][3] + p1.y + biasS[nloc + 1] };
                *(float2*)(out + (size_t)m0 * OUT_DIM + bn0 + nloc)       = v0;
                *(float2*)(out + (size_t)(m0 + 8) * OUT_DIM + bn0 + nloc) = v1;
            }
        }
    }
}

// ---------------- launcher ----------------
extern "C" void kernel_launch(void* const* d_in, const int* in_sizes, int n_in,
                              void* d_out, int out_size) {
    const float* X    = (const float*)d_in[0];
    const float* W    = (const float*)d_in[1];
    const float* bias = (const float*)d_in[2];
    float* out = (float*)d_out;
    (void)in_sizes; (void)n_in; (void)out_size;

    dim3 pgrid(KTOT / 32, OUT_DIM / 32);
    w_prep_kernel<<<pgrid, dim3(32, 8)>>>(W);

    cudaFuncSetAttribute(fkan_ws_kernel,
                         cudaFuncAttributeMaxDynamicSharedMemorySize, SM_TOTAL);
    dim3 grid(OUT_DIM / BN, BATCH / BM);
    fkan_ws_kernel<<<grid, THREADS, SM_TOTAL>>>(X, bias, out);
}